// round 3
// baseline (speedup 1.0000x reference)
#include <cuda_runtime.h>

// SmoothRankAP (quick_forward, sigmoid, tau=0.01), B=512. Single fused kernel.
// sigma(x) = 0.5*tanh(x/2)+0.5 with h = scores*50.
//   sim_all(q,i) = 0.5*T_all + 256.5,  T_all = sum_j tanh(h_j - h_i)
//   sim_pos(q,i) = 0.5*(T_pos - tanh(h_q - h_i) + npos) + 0.5,  T_pos = sum_j tanh(h_j-h_i)*t_j
// 2 rows per block (256 blocks): warps 0-3 -> row 0, warps 4-7 -> row 1.
// Per-lane register cache of h/t removes all inner-loop LDS; pairs processed
// two-at-a-time so the shuffle reduce is amortized and 4-wide ILP.

static constexpr int BB = 512;

__device__ float        g_ap[BB];
__device__ unsigned int g_ticket = 0;   // reset by last block -> deterministic graph replays

__device__ __forceinline__ float tanh_approx(float x) {
    float y;
    asm("tanh.approx.f32 %0, %1;" : "=f"(y) : "f"(x));
    return y;
}

__global__ __launch_bounds__(256) void smoothap_fused_kernel(
    const float* __restrict__ scores,
    const float* __restrict__ target,
    float* __restrict__ out)
{
    __shared__ float hs[2][BB];
    __shared__ float ts[2][BB];
    __shared__ int   poslist[2][BB];
    __shared__ int   c_cnt[2][16];     // counts, then exclusive offsets
    __shared__ int   npos_s[2];
    __shared__ float warp_acc[8];
    __shared__ int   is_last_s;

    const int tid  = threadIdx.x;
    const int wid  = tid >> 5;
    const int lane = tid & 31;
    const int q0   = blockIdx.x * 2;

    // ---- stage 2 contiguous rows: 256 float4 each for scores and target ----
    {
        float4 v = reinterpret_cast<const float4*>(scores + (size_t)q0 * BB)[tid];
        float4 w = reinterpret_cast<const float4*>(target + (size_t)q0 * BB)[tid];
        const int r = tid >> 7;              // 128 float4 per row
        const int c = (tid & 127) * 4;
        hs[r][c + 0] = v.x * 50.0f; hs[r][c + 1] = v.y * 50.0f;
        hs[r][c + 2] = v.z * 50.0f; hs[r][c + 3] = v.w * 50.0f;
        ts[r][c + 0] = w.x; ts[r][c + 1] = w.y;
        ts[r][c + 2] = w.z; ts[r][c + 3] = w.w;
    }
    __syncthreads();

    const int r  = wid >> 2;        // this warp's row (0/1)
    const int lw = wid & 3;         // warp index within row group

    // ---- order-preserving ballot compaction of positives (16 chunks/row) ----
    #pragma unroll
    for (int k = 0; k < 4; ++k) {
        const int c = lw * 4 + k;
        unsigned m = __ballot_sync(0xffffffffu, ts[r][c * 32 + lane] > 0.5f);
        if (lane == 0) c_cnt[r][c] = __popc(m);
    }
    __syncthreads();
    if (tid < 2) {                  // tiny serial exclusive scan per row
        int run = 0;
        #pragma unroll
        for (int c = 0; c < 16; ++c) { int v = c_cnt[tid][c]; c_cnt[tid][c] = run; run += v; }
        npos_s[tid] = run;
    }
    __syncthreads();
    #pragma unroll
    for (int k = 0; k < 4; ++k) {
        const int c = lw * 4 + k;
        const int j = c * 32 + lane;
        const bool p = ts[r][j] > 0.5f;
        unsigned m = __ballot_sync(0xffffffffu, p);
        if (p) poslist[r][c_cnt[r][c] + __popc(m & ((1u << lane) - 1u))] = j;
    }

    // ---- per-lane register cache of this row's h and t ----
    float hreg[16], treg[16];
    #pragma unroll
    for (int k = 0; k < 16; ++k) {
        hreg[k] = hs[r][k * 32 + lane];
        treg[k] = ts[r][k * 32 + lane];
    }
    __syncthreads();

    const int   npos = npos_s[r];          // >= 1 (diagonal)
    const float fnp  = (float)npos;
    const float hq   = hs[r][q0 + r];
    float acc = 0.0f;                      // meaningful on lane 0

    for (int pa = lw; pa < npos; pa += 8) {
        const int pb = pa + 4;
        if (pb < npos) {
            const float hiA = hs[r][poslist[r][pa]];
            const float hiB = hs[r][poslist[r][pb]];
            float aA = 0.0f, pA = 0.0f, aB = 0.0f, pB = 0.0f;
            #pragma unroll
            for (int k = 0; k < 16; ++k) {
                const float thA = tanh_approx(hreg[k] - hiA);
                const float thB = tanh_approx(hreg[k] - hiB);
                aA += thA; pA = fmaf(thA, treg[k], pA);
                aB += thB; pB = fmaf(thB, treg[k], pB);
            }
            #pragma unroll
            for (int o = 16; o; o >>= 1) {
                aA += __shfl_xor_sync(0xffffffffu, aA, o);
                pA += __shfl_xor_sync(0xffffffffu, pA, o);
                aB += __shfl_xor_sync(0xffffffffu, aB, o);
                pB += __shfl_xor_sync(0xffffffffu, pB, o);
            }
            if (lane == 0) {
                const float thqA = tanh_approx(hq - hiA);
                const float thqB = tanh_approx(hq - hiB);
                acc += __fdividef(0.5f * (pA - thqA + fnp) + 0.5f, 0.5f * aA + 256.5f);
                acc += __fdividef(0.5f * (pB - thqB + fnp) + 0.5f, 0.5f * aB + 256.5f);
            }
        } else {
            const float hiA = hs[r][poslist[r][pa]];
            float aA = 0.0f, pA = 0.0f;
            #pragma unroll
            for (int k = 0; k < 16; ++k) {
                const float thA = tanh_approx(hreg[k] - hiA);
                aA += thA; pA = fmaf(thA, treg[k], pA);
            }
            #pragma unroll
            for (int o = 16; o; o >>= 1) {
                aA += __shfl_xor_sync(0xffffffffu, aA, o);
                pA += __shfl_xor_sync(0xffffffffu, pA, o);
            }
            if (lane == 0) {
                const float thqA = tanh_approx(hq - hiA);
                acc += __fdividef(0.5f * (pA - thqA + fnp) + 0.5f, 0.5f * aA + 256.5f);
            }
        }
    }

    if (lane == 0) warp_acc[wid] = acc;
    __syncthreads();

    if ((tid & 127) == 0) {                // tid 0 -> row 0, tid 128 -> row 1
        const int rr = tid >> 7;
        float tot = 0.0f;
        #pragma unroll
        for (int w = 0; w < 4; ++w) tot += warp_acc[rr * 4 + w];
        g_ap[q0 + rr] = __fdividef(tot, (float)npos_s[rr]);
        __threadfence();                   // publish before ticket
    }
    __syncthreads();
    if (tid == 0) {
        unsigned tk = atomicAdd(&g_ticket, 1u);
        is_last_s = (tk == (unsigned)(gridDim.x - 1));
    }
    __syncthreads();

    // ---- last block: deterministic final reduction (1 sync) ----
    if (is_last_s) {
        float v = __ldcg(&g_ap[tid]) + __ldcg(&g_ap[tid + 256]);
        #pragma unroll
        for (int o = 16; o; o >>= 1) v += __shfl_xor_sync(0xffffffffu, v, o);
        if (lane == 0) warp_acc[wid] = v;
        __syncthreads();
        if (tid == 0) {
            float s = 0.0f;
            #pragma unroll
            for (int w = 0; w < 8; ++w) s += warp_acc[w];
            out[0] = 1.0f - s * (1.0f / (float)BB);
            g_ticket = 0;                  // reset for next graph replay
        }
    }
}

extern "C" void kernel_launch(void* const* d_in, const int* in_sizes, int n_in,
                              void* d_out, int out_size)
{
    const float* scores = (const float*)d_in[0];
    const float* target = (const float*)d_in[1];
    smoothap_fused_kernel<<<BB / 2, 256>>>(scores, target, (float*)d_out);
}